// round 2
// baseline (speedup 1.0000x reference)
#include <cuda_runtime.h>
#include <math.h>

#define N_NODES 50000
#define IN_F    256
#define OUT_F   64
#define N_EDGES 1600000
#define ALPHA   0.2f

// ---------------- scratch (static device globals; no allocation) ----------------
__device__ __align__(16) float g_h[(size_t)N_NODES * OUT_F];      // 12.8 MB
__device__ __align__(16) float g_acc[(size_t)N_NODES * OUT_F];    // 12.8 MB
__device__ float g_s1[N_NODES];
__device__ float g_s2[N_NODES];
__device__ float g_rowsum[N_NODES];
__device__ float g_edgew[N_EDGES];                                // 6.4 MB

// ---------------- kernel 0: zero accumulators ----------------
__global__ void k_init() {
    int idx = blockIdx.x * blockDim.x + threadIdx.x;
    if (idx < N_NODES * OUT_F) g_acc[idx] = 0.0f;
    if (idx < N_NODES)         g_rowsum[idx] = 0.0f;
}

// ---------------- kernel 1: h = x @ W ----------------
// block = 256 threads; 32 nodes per block; thread (f = tid%64, group g = tid/64)
// computes feature f for nodes g*8 .. g*8+7 (8 accumulators per thread).
__global__ __launch_bounds__(256) void k_gemm(const float* __restrict__ x,
                                              const float* __restrict__ W) {
    __shared__ __align__(16) float xs[32 * IN_F];  // 32 KB
    const int tid = threadIdx.x;
    const int nodeBase = blockIdx.x * 32;

    // cooperative load of 32 x-rows into shared (float4)
    for (int i = tid; i < 32 * IN_F / 4; i += 256) {
        int row  = i >> 6;          // 64 float4 per row
        int node = nodeBase + row;
        float4 v = make_float4(0.f, 0.f, 0.f, 0.f);
        if (node < N_NODES)
            v = ((const float4*)(x + (size_t)node * IN_F))[i & 63];
        ((float4*)xs)[i] = v;
    }
    __syncthreads();

    const int f = tid & 63;
    const int g = tid >> 6;  // 0..3
    float acc[8] = {0.f, 0.f, 0.f, 0.f, 0.f, 0.f, 0.f, 0.f};

    #pragma unroll 4
    for (int k0 = 0; k0 < IN_F; k0 += 4) {
        float w0 = W[(k0 + 0) * OUT_F + f];
        float w1 = W[(k0 + 1) * OUT_F + f];
        float w2 = W[(k0 + 2) * OUT_F + f];
        float w3 = W[(k0 + 3) * OUT_F + f];
        #pragma unroll
        for (int j = 0; j < 8; j++) {
            const float4 xv = *(const float4*)&xs[(g * 8 + j) * IN_F + k0];
            acc[j] = fmaf(xv.x, w0, acc[j]);
            acc[j] = fmaf(xv.y, w1, acc[j]);
            acc[j] = fmaf(xv.z, w2, acc[j]);
            acc[j] = fmaf(xv.w, w3, acc[j]);
        }
    }

    #pragma unroll
    for (int j = 0; j < 8; j++) {
        int node = nodeBase + g * 8 + j;
        if (node < N_NODES) g_h[(size_t)node * OUT_F + f] = acc[j];
    }
}

// ---------------- kernel 2: s1 = h@a1, s2 = h@a2 (one warp per node) ----------------
__global__ __launch_bounds__(128) void k_scores(const float* __restrict__ a) {
    int warp = (blockIdx.x * blockDim.x + threadIdx.x) >> 5;
    int lane = threadIdx.x & 31;
    if (warp >= N_NODES) return;
    float h0 = g_h[(size_t)warp * OUT_F + lane];
    float h1 = g_h[(size_t)warp * OUT_F + 32 + lane];
    float p1 = h0 * a[lane]      + h1 * a[lane + 32];
    float p2 = h0 * a[64 + lane] + h1 * a[96 + lane];
    #pragma unroll
    for (int o = 16; o; o >>= 1) {
        p1 += __shfl_xor_sync(0xFFFFFFFFu, p1, o);
        p2 += __shfl_xor_sync(0xFFFFFFFFu, p2, o);
    }
    if (lane == 0) { g_s1[warp] = p1; g_s2[warp] = p2; }
}

// ---------------- kernel 3: per-edge weight + rowsum atomic ----------------
__global__ __launch_bounds__(256) void k_edge(const int* __restrict__ ei) {
    int e = blockIdx.x * blockDim.x + threadIdx.x;
    if (e >= N_EDGES) return;
    int src = ei[e];
    int dst = ei[N_EDGES + e];
    float s  = g_s1[src] + g_s2[dst];
    float lr = s > 0.f ? s : ALPHA * s;
    float w  = expf(-lr);
    g_edgew[e] = w;
    atomicAdd(&g_rowsum[src], w);
}

// ---------------- kernel 4: scatter acc[src] += w * h[dst] (vector RED) ----------------
// 16 threads per edge; each handles one float4 chunk of the 64 features.
__global__ __launch_bounds__(256) void k_scatter(const int* __restrict__ ei) {
    long long idx = (long long)blockIdx.x * blockDim.x + threadIdx.x;
    if (idx >= (long long)N_EDGES * 16) return;
    int e = (int)(idx >> 4);
    int c = (int)(idx & 15);
    int src = ei[e];
    int dst = ei[N_EDGES + e];
    float w = g_edgew[e];
    float4 hv = ((const float4*)g_h)[(size_t)dst * 16 + c];
    float4 v  = make_float4(w * hv.x, w * hv.y, w * hv.z, w * hv.w);
    float4* p = ((float4*)g_acc) + (size_t)src * 16 + c;
    asm volatile("red.global.add.v4.f32 [%0], {%1, %2, %3, %4};"
                 :: "l"(p), "f"(v.x), "f"(v.y), "f"(v.z), "f"(v.w)
                 : "memory");
}

// ---------------- kernel 5: finalize out = elu(acc / rowsum) ----------------
__global__ __launch_bounds__(256) void k_final(float* __restrict__ out) {
    int idx = blockIdx.x * blockDim.x + threadIdx.x;
    if (idx >= N_NODES * OUT_F) return;
    float v = g_acc[idx] / g_rowsum[idx >> 6];
    out[idx] = v > 0.f ? v : expm1f(v);
}

// ---------------- launch ----------------
extern "C" void kernel_launch(void* const* d_in, const int* in_sizes, int n_in,
                              void* d_out, int out_size) {
    const float* x  = (const float*)d_in[0];
    const float* W  = (const float*)d_in[1];
    const float* a  = (const float*)d_in[2];
    const int*   ei = (const int*)d_in[3];
    float* out = (float*)d_out;

    (void)in_sizes; (void)n_in; (void)out_size;

    k_init<<<(N_NODES * OUT_F + 255) / 256, 256>>>();
    k_gemm<<<(N_NODES + 31) / 32, 256>>>(x, W);
    k_scores<<<(N_NODES * 32 + 127) / 128, 128>>>(a);
    k_edge<<<(N_EDGES + 255) / 256, 256>>>(ei);
    {
        long long total = (long long)N_EDGES * 16;
        int blocks = (int)((total + 255) / 256);
        k_scatter<<<blocks, 256>>>(ei);
    }
    k_final<<<(N_NODES * OUT_F + 255) / 256, 256>>>(out);
}